// round 8
// baseline (speedup 1.0000x reference)
#include <cuda_runtime.h>
#include <cuda_bf16.h>
#include <cuda_fp16.h>
#include <math.h>
#include <stdint.h>

#define LNUM 4
#define BB   64
#define NNODE 511
#define SS   512
#define DD   256
#define HH   8
#define HDIM 32
#define DFFN 512
#define MTOK (BB*SS)          /* 32768 */

typedef unsigned long long ull;

/* ------------------------------------------------------------------ */
/* Scratch (device globals; no allocations allowed)                    */
/* ------------------------------------------------------------------ */
__device__ float g_x  [(size_t)MTOK*DD];        /* residual stream */
__device__ float g_h  [(size_t)MTOK*DD];        /* layernorm out   */
__device__ float g_qkv[(size_t)MTOK*3*DD];      /* qkv             */
__device__ float g_o  [(size_t)MTOK*DD];        /* attn out        */
__device__ float g_ff [(size_t)MTOK*DFFN];      /* ff intermediate */
__device__ unsigned char g_et[(size_t)BB*NNODE*512];

/* ------------------------------------------------------------------ */
/* helpers                                                             */
/* ------------------------------------------------------------------ */
__device__ __forceinline__ ull pk2(float lo, float hi) {
    ull r; asm("mov.b64 %0, {%1,%2};" : "=l"(r) : "f"(lo), "f"(hi)); return r;
}
__device__ __forceinline__ float2 upk2(ull v) {
    float2 f; asm("mov.b64 {%0,%1}, %2;" : "=f"(f.x), "=f"(f.y) : "l"(v)); return f;
}
__device__ __forceinline__ ull ffma2(ull a, ull b, ull c) {
    ull d; asm("fma.rn.f32x2 %0, %1, %2, %3;" : "=l"(d) : "l"(a), "l"(b), "l"(c)); return d;
}
__device__ __forceinline__ uint32_t f2tf(float x) {
    uint32_t r; asm("cvt.rna.tf32.f32 %0, %1;" : "=r"(r) : "f"(x)); return r;
}
__device__ __forceinline__ void mma_tf32(float* c, const uint4& a, const uint2& b) {
    asm volatile(
        "mma.sync.aligned.m16n8k8.row.col.f32.tf32.tf32.f32 "
        "{%0,%1,%2,%3}, {%4,%5,%6,%7}, {%8,%9}, {%0,%1,%2,%3};"
        : "+f"(c[0]), "+f"(c[1]), "+f"(c[2]), "+f"(c[3])
        : "r"(a.x), "r"(a.y), "r"(a.z), "r"(a.w), "r"(b.x), "r"(b.y));
}

/* ------------------------------------------------------------------ */
/* embed + edge-type compress                                          */
/* ------------------------------------------------------------------ */
__global__ void embed_kernel(const int* __restrict__ cs,
                             const float* __restrict__ patch_emb,
                             const float* __restrict__ game_token) {
    int row = blockIdx.x;
    int d   = threadIdx.x;
    int b = row >> 9, s = row & 511;
    float v;
    if (s == 0) v = game_token[d];
    else        v = patch_emb[cs[b*NNODE + s - 1]*DD + d];
    g_x[(size_t)row*DD + d] = v;
}

__global__ void etcomp_kernel(const int* __restrict__ etm) {
    int i = blockIdx.x*blockDim.x + threadIdx.x;
    const int total = BB*NNODE*NNODE;
    if (i >= total) return;
    int b = i / (NNODE*NNODE);
    int r = i - b*(NNODE*NNODE);
    int q = r / NNODE;
    int k = r - q*NNODE;
    g_et[((size_t)(b*NNODE + q))*512 + k] = (unsigned char)etm[i];
}

/* ------------------------------------------------------------------ */
/* layernorm: g_h = LN(g_x)*gamma + beta   (one warp per row)          */
/* ------------------------------------------------------------------ */
__global__ void ln_kernel(const float* __restrict__ gam, const float* __restrict__ bet) {
    int w = threadIdx.x >> 5, lane = threadIdx.x & 31;
    int row = blockIdx.x*8 + w;
    const float* xr = g_x + (size_t)row*DD;
    float4 v0 = *(const float4*)(xr + lane*8);
    float4 v1 = *(const float4*)(xr + lane*8 + 4);
    float s = v0.x+v0.y+v0.z+v0.w + v1.x+v1.y+v1.z+v1.w;
    float q = v0.x*v0.x+v0.y*v0.y+v0.z*v0.z+v0.w*v0.w
            + v1.x*v1.x+v1.y*v1.y+v1.z*v1.z+v1.w*v1.w;
#pragma unroll
    for (int o = 16; o; o >>= 1) {
        s += __shfl_xor_sync(0xffffffffu, s, o);
        q += __shfl_xor_sync(0xffffffffu, q, o);
    }
    float m   = s * (1.f/256.f);
    float var = q * (1.f/256.f) - m*m;
    float rs  = rsqrtf(var + 1e-5f);
    int d = lane*8;
    float4 ga = *(const float4*)(gam + d);
    float4 gb = *(const float4*)(gam + d + 4);
    float4 ba = *(const float4*)(bet + d);
    float4 bb = *(const float4*)(bet + d + 4);
    float4 o0, o1;
    o0.x = (v0.x-m)*rs*ga.x + ba.x;  o0.y = (v0.y-m)*rs*ga.y + ba.y;
    o0.z = (v0.z-m)*rs*ga.z + ba.z;  o0.w = (v0.w-m)*rs*ga.w + ba.w;
    o1.x = (v1.x-m)*rs*gb.x + bb.x;  o1.y = (v1.y-m)*rs*gb.y + bb.y;
    o1.z = (v1.z-m)*rs*gb.z + bb.z;  o1.w = (v1.w-m)*rs*gb.w + bb.w;
    float* hr = g_h + (size_t)row*DD;
    *(float4*)(hr + lane*8)     = o0;
    *(float4*)(hr + lane*8 + 4) = o1;
}

/* ------------------------------------------------------------------ */
/* TF32 tensor-core GEMM: C[M,Nn] (+)= A[M,K] @ W[Nn,K]^T + bias       */
/* hi/lo tf32 split (3 mmas). CTA 128x128, warp 64x32, K-chunks 16.    */
/* Smem in fragment-ready layout; double buffered.                     */
/* VAR: 0 plain, 1 relu, 2 residual add                                */
/* ------------------------------------------------------------------ */
#define GEMM_SMEM_FLOATS (2*8192)
#define GEMM_SMEM_BYTES  (GEMM_SMEM_FLOATS*4)

template<int VAR>
__global__ void __launch_bounds__(256)
gemm_mma(const float* __restrict__ A, const float* __restrict__ W,
         const float* __restrict__ bias, float* __restrict__ C,
         int Nn, int K)
{
    extern __shared__ float sm[];
    const int t    = threadIdx.x;
    const int lane = t & 31;
    const int wid  = t >> 5;
    const int wm   = wid & 1;           /* M half   (64 rows)  */
    const int wn   = wid >> 1;          /* N quarter (32 cols) */
    const int m0   = blockIdx.y * 128;
    const int n0   = blockIdx.x * 128;
    const int NC   = K >> 4;

    const int srow = t >> 1;            /* staging row 0..127 */
    const int kh   = t & 1;             /* k half: 8 floats   */
    const float* gA = A + (size_t)(m0 + srow)*K + kh*8;
    const float* gB = W + (size_t)(n0 + srow)*K + kh*8;

    /* staging destination bases (frag-ready layout) */
    const int mtile = srow >> 4, mm = srow & 15;
    const int ntile = srow >> 3, nn = srow & 7;
    const int aBlk = ((mtile*2 + kh)*2) * 128;   /* hl=0 base; +128 for lo */
    const int bBlk = 4096 + ((ntile*2 + kh)*2) * 64;

    float acc[4][4][4];
#pragma unroll
    for (int i = 0; i < 4; ++i)
#pragma unroll
        for (int j = 0; j < 4; ++j)
#pragma unroll
            for (int q = 0; q < 4; ++q) acc[i][j][q] = 0.f;

    float aR[8], bR[8];
    /* load + stage chunk 0 */
    {
        float4 x0 = *(const float4*)(gA);
        float4 x1 = *(const float4*)(gA + 4);
        aR[0]=x0.x; aR[1]=x0.y; aR[2]=x0.z; aR[3]=x0.w;
        aR[4]=x1.x; aR[5]=x1.y; aR[6]=x1.z; aR[7]=x1.w;
        float4 y0 = *(const float4*)(gB);
        float4 y1 = *(const float4*)(gB + 4);
        bR[0]=y0.x; bR[1]=y0.y; bR[2]=y0.z; bR[3]=y0.w;
        bR[4]=y1.x; bR[5]=y1.y; bR[6]=y1.z; bR[7]=y1.w;
    }
    {
        uint32_t* dst = (uint32_t*)sm;
#pragma unroll
        for (int i = 0; i < 8; ++i) {
            uint32_t hi = f2tf(aR[i]);
            uint32_t lo = f2tf(aR[i] - __uint_as_float(hi));
            int pos = aBlk + (((mm&7)<<2) + (i&3))*4 + ((mm>>3) + ((i>>2)<<1));
            dst[pos] = hi; dst[pos + 128] = lo;
        }
#pragma unroll
        for (int i = 0; i < 8; ++i) {
            uint32_t hi = f2tf(bR[i]);
            uint32_t lo = f2tf(bR[i] - __uint_as_float(hi));
            int pos = bBlk + ((nn<<2) + (i&3))*2 + (i>>2);
            dst[pos] = hi; dst[pos + 64] = lo;
        }
    }
    __syncthreads();

    for (int c = 0; c < NC; ++c) {
        const int buf = c & 1;
        if (c + 1 < NC) {
            const float* pa = gA + (c+1)*16;
            const float* pb = gB + (c+1)*16;
            float4 x0 = *(const float4*)(pa);
            float4 x1 = *(const float4*)(pa + 4);
            aR[0]=x0.x; aR[1]=x0.y; aR[2]=x0.z; aR[3]=x0.w;
            aR[4]=x1.x; aR[5]=x1.y; aR[6]=x1.z; aR[7]=x1.w;
            float4 y0 = *(const float4*)(pb);
            float4 y1 = *(const float4*)(pb + 4);
            bR[0]=y0.x; bR[1]=y0.y; bR[2]=y0.z; bR[3]=y0.w;
            bR[4]=y1.x; bR[5]=y1.y; bR[6]=y1.z; bR[7]=y1.w;
        }
        /* compute from buf */
        {
            const uint32_t* base = (const uint32_t*)(sm + buf*8192);
#pragma unroll
            for (int ks = 0; ks < 2; ++ks) {
                uint4 ah[4], al[4];
                uint2 bh[4], bl[4];
#pragma unroll
                for (int mt = 0; mt < 4; ++mt) {
                    const uint32_t* p = base + (((wm*4 + mt)*2 + ks)*2)*128 + lane*4;
                    ah[mt] = *(const uint4*)p;
                    al[mt] = *(const uint4*)(p + 128);
                }
#pragma unroll
                for (int nt = 0; nt < 4; ++nt) {
                    const uint32_t* p = base + 4096 + (((wn*4 + nt)*2 + ks)*2)*64 + lane*2;
                    bh[nt] = *(const uint2*)p;
                    bl[nt] = *(const uint2*)(p + 64);
                }
#pragma unroll
                for (int mt = 0; mt < 4; ++mt)
#pragma unroll
                    for (int nt = 0; nt < 4; ++nt) {
                        mma_tf32(acc[mt][nt], ah[mt], bh[nt]);
                        mma_tf32(acc[mt][nt], ah[mt], bl[nt]);
                        mma_tf32(acc[mt][nt], al[mt], bh[nt]);
                    }
            }
        }
        if (c + 1 < NC) {
            uint32_t* dst = (uint32_t*)(sm + (buf^1)*8192);
#pragma unroll
            for (int i = 0; i < 8; ++i) {
                uint32_t hi = f2tf(aR[i]);
                uint32_t lo = f2tf(aR[i] - __uint_as_float(hi));
                int pos = aBlk + (((mm&7)<<2) + (i&3))*4 + ((mm>>3) + ((i>>2)<<1));
                dst[pos] = hi; dst[pos + 128] = lo;
            }
#pragma unroll
            for (int i = 0; i < 8; ++i) {
                uint32_t hi = f2tf(bR[i]);
                uint32_t lo = f2tf(bR[i] - __uint_as_float(hi));
                int pos = bBlk + ((nn<<2) + (i&3))*2 + (i>>2);
                dst[pos] = hi; dst[pos + 64] = lo;
            }
            __syncthreads();
        }
    }

    /* epilogue */
#pragma unroll
    for (int mt = 0; mt < 4; ++mt) {
#pragma unroll
        for (int nt = 0; nt < 4; ++nt) {
            int r0 = m0 + wm*64 + mt*16 + (lane >> 2);
            int cc = n0 + wn*32 + nt*8 + ((lane & 3) << 1);
            float b0 = bias[cc], b1 = bias[cc + 1];
            float v0 = acc[mt][nt][0] + b0;
            float v1 = acc[mt][nt][1] + b1;
            float v2 = acc[mt][nt][2] + b0;
            float v3 = acc[mt][nt][3] + b1;
            if (VAR == 1) {
                v0 = fmaxf(v0, 0.f); v1 = fmaxf(v1, 0.f);
                v2 = fmaxf(v2, 0.f); v3 = fmaxf(v3, 0.f);
            }
            float* p0 = C + (size_t)r0*Nn + cc;
            float* p1 = C + (size_t)(r0 + 8)*Nn + cc;
            if (VAR == 2) {
                float2 o0 = *(float2*)p0, o1 = *(float2*)p1;
                v0 += o0.x; v1 += o0.y; v2 += o1.x; v3 += o1.y;
            }
            *(float2*)p0 = make_float2(v0, v1);
            *(float2*)p1 = make_float2(v2, v3);
        }
    }
}

/* ------------------------------------------------------------------ */
/* fused attention: one block of 512 threads per (b,h)                 */
/* 16 warps x 4 q-rows x 8 iterations                                  */
/* probs stay fp32; PV transpose via small per-warp chunk buffer       */
/* ------------------------------------------------------------------ */
#define KS_LD 516
#define ATT_KS 0
#define ATT_VS 16512                       /* 32*516 */
#define ATT_QS 32896                       /* +512*32 */
#define ATT_PC 34944                       /* +16*128 */
#define ATTN_SMEM_FLOATS (34944 + 16*512)  /* + per-warp chunk bufs */
#define ATTN_SMEM_BYTES  (ATTN_SMEM_FLOATS*4)

__global__ void __launch_bounds__(512)
attn_kernel(const float* __restrict__ edge_emb) {
    extern __shared__ float sm[];
    float* Ks = sm + ATT_KS;                 /* [32][516] transposed */
    float* Vs = sm + ATT_VS;                 /* [512][32]            */
    float* qs = sm + ATT_QS;                 /* [16][128]            */

    const int bh = blockIdx.x;
    const int b  = bh >> 3, h = bh & 7;
    const int t  = threadIdx.x;
    const int w  = t >> 5, lane = t & 31;

    const float eb0 = edge_emb[0*HH + h];
    const float eb1 = edge_emb[1*HH + h];
    const float eb2 = edge_emb[2*HH + h];

    const float* base = g_qkv + ((size_t)b*SS)*768 + h*HDIM;
    for (int it = 0; it < 32; ++it) {
        int s = it*16 + w;
        Ks[lane*KS_LD + s] = base[(size_t)s*768 + 256 + lane];
        Vs[s*32 + lane]    = base[(size_t)s*768 + 512 + lane];
    }
    __syncthreads();

    float* pcw = sm + ATT_PC + w*512;        /* [128] x float4       */
    float* qw  = qs + w*128;
    const float inv = 0.17677669529663687f;

    for (int gi = 0; gi < 8; ++gi) {
        const int q0 = (gi*16 + w)*4;
#pragma unroll
        for (int r = 0; r < 4; ++r)
            qw[lane*4 + r] = base[(size_t)(q0 + r)*768 + lane];
        __syncwarp();

        ull acc[16][2];
#pragma unroll
        for (int j = 0; j < 16; ++j) { acc[j][0] = pk2(0.f,0.f); acc[j][1] = pk2(0.f,0.f); }

#pragma unroll 4
        for (int d = 0; d < 32; ++d) {
            float4 qv = *(const float4*)&qw[d*4];
            ull qp0 = pk2(qv.x, qv.y), qp1 = pk2(qv.z, qv.w);
            const float* kr = &Ks[d*KS_LD + lane*16];
            float4 k0 = ((const float4*)kr)[0];
            float4 k1 = ((const float4*)kr)[1];
            float4 k2 = ((const float4*)kr)[2];
            float4 k3 = ((const float4*)kr)[3];
            float kvals[16] = {k0.x,k0.y,k0.z,k0.w, k1.x,k1.y,k1.z,k1.w,
                               k2.x,k2.y,k2.z,k2.w, k3.x,k3.y,k3.z,k3.w};
#pragma unroll
            for (int j = 0; j < 16; ++j) {
                ull bd = pk2(kvals[j], kvals[j]);
                acc[j][0] = ffma2(qp0, bd, acc[j][0]);
                acc[j][1] = ffma2(qp1, bd, acc[j][1]);
            }
        }

        float pbuf[4][16];
#pragma unroll
        for (int j = 0; j < 16; ++j) {
            float2 fa = upk2(acc[j][0]);
            float2 fb = upk2(acc[j][1]);
            pbuf[0][j] = fa.x; pbuf[1][j] = fa.y; pbuf[2][j] = fb.x; pbuf[3][j] = fb.y;
        }

#pragma unroll
        for (int r = 0; r < 4; ++r) {
            int q = q0 + r;
            if (q > 0) {
                const unsigned char* etr = g_et + ((size_t)(b*NNODE + (q-1)))*512;
                uint4 ev = *(const uint4*)(etr + lane*16);
                unsigned int wd[4] = {ev.x, ev.y, ev.z, ev.w};
                unsigned int last = (ev.w >> 24) & 0xffu;
                unsigned int prev = __shfl_up_sync(0xffffffffu, last, 1);
#pragma unroll
                for (int j = 0; j < 16; ++j) {
                    float bi;
                    if (j == 0) {
                        bi = (lane == 0) ? 0.f
                             : (prev == 0u ? eb0 : (prev == 1u ? eb1 : eb2));
                    } else {
                        unsigned int e = (wd[(j-1)>>2] >> (8*((j-1)&3))) & 0xffu;
                        bi = (e == 0u ? eb0 : (e == 1u ? eb1 : eb2));
                    }
                    pbuf[r][j] = pbuf[r][j]*inv + bi;
                }
            } else {
#pragma unroll
                for (int j = 0; j < 16; ++j) pbuf[r][j] *= inv;
            }
        }

#pragma unroll
        for (int r = 0; r < 4; ++r) {
            float m = -1e30f;
#pragma unroll
            for (int j = 0; j < 16; ++j) m = fmaxf(m, pbuf[r][j]);
#pragma unroll
            for (int o = 16; o; o >>= 1) m = fmaxf(m, __shfl_xor_sync(0xffffffffu, m, o));
            float s = 0.f;
#pragma unroll
            for (int j = 0; j < 16; ++j) { pbuf[r][j] = __expf(pbuf[r][j] - m); s += pbuf[r][j]; }
#pragma unroll
            for (int o = 16; o; o >>= 1) s += __shfl_xor_sync(0xffffffffu, s, o);
            float is = 1.f / s;
#pragma unroll
            for (int j = 0; j < 16; ++j) pbuf[r][j] *= is;
        }

        /* PV in 4 chunks of 4 j-slots: fp32 probs through 2KB/warp buffer */
        ull a01 = pk2(0.f,0.f), a23 = pk2(0.f,0.f);
#pragma unroll
        for (int c = 0; c < 4; ++c) {
#pragma unroll
            for (int jj = 0; jj < 4; ++jj) {
                int j = c*4 + jj;
                *(float4*)&pcw[(jj*32 + lane)*4] =
                    make_float4(pbuf[0][j], pbuf[1][j], pbuf[2][j], pbuf[3][j]);
            }
            __syncwarp();
#pragma unroll 4
            for (int s = 0; s < 128; ++s) {
                float4 pv = *(const float4*)&pcw[s*4];
                int key = ((s & 31) << 4) + c*4 + (s >> 5);
                float v = Vs[key*32 + lane];
                ull vd = pk2(v, v);
                a01 = ffma2(pk2(pv.x, pv.y), vd, a01);
                a23 = ffma2(pk2(pv.z, pv.w), vd, a23);
            }
            __syncwarp();
        }
        float2 oa = upk2(a01), ob = upk2(a23);
        float* op = g_o + ((size_t)b*SS + q0)*DD + h*HDIM + lane;
        op[0]    = oa.x;
        op[DD]   = oa.y;
        op[2*DD] = ob.x;
        op[3*DD] = ob.y;
        __syncwarp();
    }
}

/* ------------------------------------------------------------------ */
/* head                                                                */
/* ------------------------------------------------------------------ */
__global__ void head_kernel(const float* __restrict__ fc1w, const float* __restrict__ fc1b,
                            const float* __restrict__ polw, const float* __restrict__ polb,
                            const float* __restrict__ valw, const float* __restrict__ valb,
                            float* __restrict__ out) {
    __shared__ float gs[256];
    __shared__ float os[64];
    int b = blockIdx.x, t = threadIdx.x;
    const float* xr = g_x + ((size_t)b*SS)*DD;
#pragma unroll
    for (int i = 0; i < 4; ++i) gs[t + i*64] = xr[t + i*64];
    __syncthreads();
    float a = fc1b[t];
#pragma unroll 8
    for (int k = 0; k < 256; ++k) a += gs[k] * fc1w[t*256 + k];
    os[t] = fmaxf(a, 0.f);
    __syncthreads();
    if (t < 7) {
        float pacc = polb[t];
#pragma unroll
        for (int j = 0; j < 64; ++j) pacc += os[j] * polw[t*64 + j];
        out[b*7 + t] = pacc;
    }
    if (t == 7) {
        float va = valb[0];
#pragma unroll
        for (int j = 0; j < 64; ++j) va += os[j] * valw[j];
        out[BB*7 + b] = tanhf(va);
    }
}

/* ------------------------------------------------------------------ */
extern "C" void kernel_launch(void* const* d_in, const int* in_sizes, int n_in,
                              void* d_out, int out_size) {
    const int*   cs    = (const int*)d_in[0];
    const int*   etm   = (const int*)d_in[1];
    const float* pe    = (const float*)d_in[2];
    const float* gt    = (const float*)d_in[3];
    const float* ee    = (const float*)d_in[4];
    const float* in_w  = (const float*)d_in[5];
    const float* in_b  = (const float*)d_in[6];
    const float* outw  = (const float*)d_in[7];
    const float* outb  = (const float*)d_in[8];
    const float* ff1w  = (const float*)d_in[9];
    const float* ff1b  = (const float*)d_in[10];
    const float* ff2w  = (const float*)d_in[11];
    const float* ff2b  = (const float*)d_in[12];
    const float* ln1g  = (const float*)d_in[13];
    const float* ln1b  = (const float*)d_in[14];
    const float* ln2g  = (const float*)d_in[15];
    const float* ln2b  = (const float*)d_in[16];
    const float* fc1w  = (const float*)d_in[17];
    const float* fc1b  = (const float*)d_in[18];
    const float* polw  = (const float*)d_in[19];
    const float* polb  = (const float*)d_in[20];
    const float* valw  = (const float*)d_in[21];
    const float* valb  = (const float*)d_in[22];
    float* out = (float*)d_out;

    float *px, *ph, *pq, *po, *pf;
    cudaGetSymbolAddress((void**)&px, g_x);
    cudaGetSymbolAddress((void**)&ph, g_h);
    cudaGetSymbolAddress((void**)&pq, g_qkv);
    cudaGetSymbolAddress((void**)&po, g_o);
    cudaGetSymbolAddress((void**)&pf, g_ff);

    cudaFuncSetAttribute(attn_kernel, cudaFuncAttributeMaxDynamicSharedMemorySize,
                         ATTN_SMEM_BYTES);
    cudaFuncSetAttribute(gemm_mma<0>, cudaFuncAttributeMaxDynamicSharedMemorySize, GEMM_SMEM_BYTES);
    cudaFuncSetAttribute(gemm_mma<1>, cudaFuncAttributeMaxDynamicSharedMemorySize, GEMM_SMEM_BYTES);
    cudaFuncSetAttribute(gemm_mma<2>, cudaFuncAttributeMaxDynamicSharedMemorySize, GEMM_SMEM_BYTES);

    embed_kernel<<<MTOK, 256>>>(cs, pe, gt);
    etcomp_kernel<<<(BB*NNODE*NNODE + 255)/256, 256>>>(etm);

    for (int i = 0; i < LNUM; ++i) {
        ln_kernel<<<MTOK/8, 256>>>(ln1g + i*DD, ln1b + i*DD);
        gemm_mma<0><<<dim3(6, 256), 256, GEMM_SMEM_BYTES>>>(
            ph, in_w + (size_t)i*768*256, in_b + i*768, pq, 768, 256);
        attn_kernel<<<BB*HH, 512, ATTN_SMEM_BYTES>>>(ee);
        gemm_mma<2><<<dim3(2, 256), 256, GEMM_SMEM_BYTES>>>(
            po, outw + (size_t)i*256*256, outb + i*256, px, 256, 256);
        ln_kernel<<<MTOK/8, 256>>>(ln2g + i*DD, ln2b + i*DD);
        gemm_mma<1><<<dim3(4, 256), 256, GEMM_SMEM_BYTES>>>(
            ph, ff1w + (size_t)i*512*256, ff1b + i*512, pf, 512, 256);
        gemm_mma<2><<<dim3(2, 256), 256, GEMM_SMEM_BYTES>>>(
            pf, ff2w + (size_t)i*256*512, ff2b + i*256, px, 256, 512);
    }
    head_kernel<<<BB, 64>>>(fc1w, fc1b, polw, polb, valw, valb, out);
}

// round 9
// speedup vs baseline: 1.8912x; 1.8912x over previous
#include <cuda_runtime.h>
#include <cuda_bf16.h>
#include <math.h>
#include <stdint.h>

#define LNUM 4
#define BB   64
#define NNODE 511
#define SS   512
#define DD   256
#define HH   8
#define HDIM 32
#define DFFN 512
#define MTOK (BB*SS)          /* 32768 */

typedef unsigned long long ull;

/* ------------------------------------------------------------------ */
/* Scratch (device globals; no allocations allowed)                    */
/* ------------------------------------------------------------------ */
__device__ float g_x  [(size_t)MTOK*DD];          /* residual stream  */
__device__ float g_qkv[(size_t)MTOK*3*DD];        /* qkv fp32         */
__device__ __nv_bfloat16 g_a_hi[(size_t)MTOK*DD]; /* activation hi    */
__device__ __nv_bfloat16 g_a_lo[(size_t)MTOK*DD]; /* activation lo    */
__device__ __nv_bfloat16 g_f_hi[(size_t)MTOK*DFFN];
__device__ __nv_bfloat16 g_f_lo[(size_t)MTOK*DFFN];
#define WTOT 2097152
__device__ __nv_bfloat16 g_w_hi[WTOT];
__device__ __nv_bfloat16 g_w_lo[WTOT];
__device__ unsigned char g_et[(size_t)BB*NNODE*512];

/* ------------------------------------------------------------------ */
/* helpers                                                             */
/* ------------------------------------------------------------------ */
__device__ __forceinline__ uint32_t smem_u32(const void* p) {
    return (uint32_t)__cvta_generic_to_shared((void*)p);
}
__device__ __forceinline__ ull pk2(float lo, float hi) {
    ull r; asm("mov.b64 %0, {%1,%2};" : "=l"(r) : "f"(lo), "f"(hi)); return r;
}
__device__ __forceinline__ float2 upk2(ull v) {
    float2 f; asm("mov.b64 {%0,%1}, %2;" : "=f"(f.x), "=f"(f.y) : "l"(v)); return f;
}
__device__ __forceinline__ ull ffma2(ull a, ull b, ull c) {
    ull d; asm("fma.rn.f32x2 %0, %1, %2, %3;" : "=l"(d) : "l"(a), "l"(b), "l"(c)); return d;
}
__device__ __forceinline__ void split_bf16(float v, __nv_bfloat16& h, __nv_bfloat16& l) {
    h = __float2bfloat16(v);
    l = __float2bfloat16(v - __bfloat162float(h));
}
__device__ __forceinline__ void cp_async16(uint32_t dst, const void* src) {
    asm volatile("cp.async.cg.shared.global [%0], [%1], 16;" :: "r"(dst), "l"(src));
}
__device__ __forceinline__ void cp_commit() {
    asm volatile("cp.async.commit_group;" ::: "memory");
}
template<int N> __device__ __forceinline__ void cp_wait() {
    asm volatile("cp.async.wait_group %0;" :: "n"(N) : "memory");
}
__device__ __forceinline__ void ldsm4(uint32_t* r, uint32_t a) {
    asm volatile("ldmatrix.sync.aligned.m8n8.x4.shared.b16 {%0,%1,%2,%3}, [%4];"
                 : "=r"(r[0]), "=r"(r[1]), "=r"(r[2]), "=r"(r[3]) : "r"(a));
}
__device__ __forceinline__ void mma_bf16(float* c, const uint32_t* a,
                                         uint32_t b0, uint32_t b1) {
    asm volatile(
        "mma.sync.aligned.m16n8k16.row.col.f32.bf16.bf16.f32 "
        "{%0,%1,%2,%3}, {%4,%5,%6,%7}, {%8,%9}, {%0,%1,%2,%3};"
        : "+f"(c[0]), "+f"(c[1]), "+f"(c[2]), "+f"(c[3])
        : "r"(a[0]), "r"(a[1]), "r"(a[2]), "r"(a[3]), "r"(b0), "r"(b1));
}

/* ------------------------------------------------------------------ */
/* embed + edge-type compress + weight split                           */
/* ------------------------------------------------------------------ */
__global__ void embed_kernel(const int* __restrict__ cs,
                             const float* __restrict__ patch_emb,
                             const float* __restrict__ game_token) {
    int row = blockIdx.x;
    int d   = threadIdx.x;
    int b = row >> 9, s = row & 511;
    float v;
    if (s == 0) v = game_token[d];
    else        v = patch_emb[cs[b*NNODE + s - 1]*DD + d];
    g_x[(size_t)row*DD + d] = v;
}

__global__ void etcomp_kernel(const int* __restrict__ etm) {
    int i = blockIdx.x*blockDim.x + threadIdx.x;
    const int total = BB*NNODE*NNODE;
    if (i >= total) return;
    int b = i / (NNODE*NNODE);
    int r = i - b*(NNODE*NNODE);
    int q = r / NNODE;
    int k = r - q*NNODE;
    g_et[((size_t)(b*NNODE + q))*512 + k] = (unsigned char)etm[i];
}

__global__ void wconv_kernel(const float* __restrict__ src, int n, int off) {
    int i = blockIdx.x*256 + threadIdx.x;
    if (i >= n) return;
    float x = src[i];
    __nv_bfloat16 h, l; split_bf16(x, h, l);
    g_w_hi[off + i] = h;
    g_w_lo[off + i] = l;
}

/* ------------------------------------------------------------------ */
/* layernorm: g_a_{hi,lo} = split(LN(g_x)*g + b)   (one warp per row)  */
/* ------------------------------------------------------------------ */
__global__ void ln_kernel(const float* __restrict__ gam, const float* __restrict__ bet) {
    int w = threadIdx.x >> 5, lane = threadIdx.x & 31;
    int row = blockIdx.x*8 + w;
    const float* xr = g_x + (size_t)row*DD;
    float4 v0 = *(const float4*)(xr + lane*8);
    float4 v1 = *(const float4*)(xr + lane*8 + 4);
    float s = v0.x+v0.y+v0.z+v0.w + v1.x+v1.y+v1.z+v1.w;
    float q = v0.x*v0.x+v0.y*v0.y+v0.z*v0.z+v0.w*v0.w
            + v1.x*v1.x+v1.y*v1.y+v1.z*v1.z+v1.w*v1.w;
#pragma unroll
    for (int o = 16; o; o >>= 1) {
        s += __shfl_xor_sync(0xffffffffu, s, o);
        q += __shfl_xor_sync(0xffffffffu, q, o);
    }
    float m   = s * (1.f/256.f);
    float var = q * (1.f/256.f) - m*m;
    float rs  = rsqrtf(var + 1e-5f);
    int d = lane*8;
    float4 ga = *(const float4*)(gam + d);
    float4 gb = *(const float4*)(gam + d + 4);
    float4 ba = *(const float4*)(bet + d);
    float4 bb = *(const float4*)(bet + d + 4);
    float o8[8];
    o8[0] = (v0.x-m)*rs*ga.x + ba.x;  o8[1] = (v0.y-m)*rs*ga.y + ba.y;
    o8[2] = (v0.z-m)*rs*ga.z + ba.z;  o8[3] = (v0.w-m)*rs*ga.w + ba.w;
    o8[4] = (v1.x-m)*rs*gb.x + bb.x;  o8[5] = (v1.y-m)*rs*gb.y + bb.y;
    o8[6] = (v1.z-m)*rs*gb.z + bb.z;  o8[7] = (v1.w-m)*rs*gb.w + bb.w;
    __nv_bfloat16* hh = g_a_hi + (size_t)row*DD + d;
    __nv_bfloat16* ll = g_a_lo + (size_t)row*DD + d;
#pragma unroll
    for (int p = 0; p < 4; ++p) {
        __nv_bfloat16 h0, l0, h1, l1;
        split_bf16(o8[2*p],   h0, l0);
        split_bf16(o8[2*p+1], h1, l1);
        __nv_bfloat162 hp; hp.x = h0; hp.y = h1;
        __nv_bfloat162 lp; lp.x = l0; lp.y = l1;
        *(__nv_bfloat162*)(hh + 2*p) = hp;
        *(__nv_bfloat162*)(ll + 2*p) = lp;
    }
}

/* ------------------------------------------------------------------ */
/* bf16 tensor-core GEMM: C[M,Nn] (+)= A[M,K] @ W[Nn,K]^T + bias       */
/* A,W pre-split bf16 hi/lo. 3 MMAs (hh,hl,lh) per tile pair.          */
/* CTA 128x128, K-chunk 32, cp.async double buffer, swizzled ldmatrix. */
/* VAR: 0 plain fp32, 1 relu, 2 residual add. WB: bf16 hi/lo output.   */
/* ------------------------------------------------------------------ */
#define GEMM_SMEM_BYTES (2*32768)

template<int VAR, int WB>
__global__ void __launch_bounds__(256)
gemm_bf(const __nv_bfloat16* __restrict__ Ahi, const __nv_bfloat16* __restrict__ Alo,
        const __nv_bfloat16* __restrict__ Whi, const __nv_bfloat16* __restrict__ Wlo,
        const float* __restrict__ bias, float* __restrict__ C,
        __nv_bfloat16* __restrict__ Ohi, __nv_bfloat16* __restrict__ Olo,
        int Nn, int K)
{
    extern __shared__ __align__(16) __nv_bfloat16 smb[];
    const int t    = threadIdx.x;
    const int lane = t & 31;
    const int wid  = t >> 5;
    const int wm   = wid & 1;           /* M half   (64 rows)  */
    const int wn   = wid >> 1;          /* N quarter (32 cols) */
    const int m0   = blockIdx.y * 128;
    const int n0   = blockIdx.x * 128;
    const int NC   = K >> 5;
    const uint32_t sb = smem_u32(smb);

    const __nv_bfloat16* mp[4] = {
        Ahi + (size_t)m0*K, Alo + (size_t)m0*K,
        Whi + (size_t)n0*K, Wlo + (size_t)n0*K };

    /* per-thread cp.async assignments: 8 chunks of 16B */
    int cid_mi[8], cid_r[8], cid_cs[8];
#pragma unroll
    for (int i = 0; i < 8; ++i) {
        int id = i*256 + t;
        cid_mi[i] = id >> 9;
        int rem = id & 511;
        cid_r[i]  = rem >> 2;
        cid_cs[i] = rem & 3;
    }

    float acc[4][4][4];
#pragma unroll
    for (int i = 0; i < 4; ++i)
#pragma unroll
        for (int j = 0; j < 4; ++j)
#pragma unroll
            for (int q = 0; q < 4; ++q) acc[i][j][q] = 0.f;

    /* issue chunk 0 */
    {
        uint32_t dbase = sb;
#pragma unroll
        for (int i = 0; i < 8; ++i) {
            int r = cid_r[i], cs = cid_cs[i], mi = cid_mi[i];
            uint32_t dst = dbase + mi*8192 + r*64 + ((cs ^ ((r>>1)&3))<<4);
            cp_async16(dst, mp[mi] + (size_t)r*K + cs*8);
        }
        cp_commit();
    }

    const int lr = lane & 15;
    const int lc = lane >> 4;

    for (int c = 0; c < NC; ++c) {
        if (c + 1 < NC) {
            int kc = (c+1) << 5;
            uint32_t dbase = sb + ((c+1)&1)*32768;
#pragma unroll
            for (int i = 0; i < 8; ++i) {
                int r = cid_r[i], cs = cid_cs[i], mi = cid_mi[i];
                uint32_t dst = dbase + mi*8192 + r*64 + ((cs ^ ((r>>1)&3))<<4);
                cp_async16(dst, mp[mi] + (size_t)r*K + kc + cs*8);
            }
            cp_commit();
            cp_wait<1>();
        } else {
            cp_wait<0>();
        }
        __syncthreads();

        uint32_t bb = sb + (c&1)*32768;
#pragma unroll
        for (int ks = 0; ks < 2; ++ks) {
            int cseg = ks*2 + lc;
            uint32_t bh[2][4], bl[2][4];
#pragma unroll
            for (int np = 0; np < 2; ++np) {
                int r = wn*32 + np*16 + lr;
                uint32_t off = r*64 + ((cseg ^ ((r>>1)&3))<<4);
                ldsm4(bh[np], bb + 2*8192 + off);
                ldsm4(bl[np], bb + 3*8192 + off);
            }
#pragma unroll
            for (int mt = 0; mt < 4; ++mt) {
                int r = wm*64 + mt*16 + lr;
                uint32_t off = r*64 + ((cseg ^ ((r>>1)&3))<<4);
                uint32_t ah[4], al[4];
                ldsm4(ah, bb + off);
                ldsm4(al, bb + 8192 + off);
#pragma unroll
                for (int nt = 0; nt < 4; ++nt) {
                    int np = nt >> 1, h2 = nt & 1;
                    mma_bf16(acc[mt][nt], ah, bh[np][h2], bh[np][h2+2]);
                    mma_bf16(acc[mt][nt], ah, bl[np][h2], bl[np][h2+2]);
                    mma_bf16(acc[mt][nt], al, bh[np][h2], bh[np][h2+2]);
                }
            }
        }
        __syncthreads();
    }

    /* epilogue */
#pragma unroll
    for (int mt = 0; mt < 4; ++mt) {
#pragma unroll
        for (int nt = 0; nt < 4; ++nt) {
            int r0 = m0 + wm*64 + mt*16 + (lane >> 2);
            int cc = n0 + wn*32 + nt*8 + ((lane & 3) << 1);
            float b0 = bias[cc], b1 = bias[cc + 1];
            float v0 = acc[mt][nt][0] + b0;
            float v1 = acc[mt][nt][1] + b1;
            float v2 = acc[mt][nt][2] + b0;
            float v3 = acc[mt][nt][3] + b1;
            if (VAR == 1) {
                v0 = fmaxf(v0, 0.f); v1 = fmaxf(v1, 0.f);
                v2 = fmaxf(v2, 0.f); v3 = fmaxf(v3, 0.f);
            }
            if (WB) {
                __nv_bfloat16 h0,l0,h1,l1;
                split_bf16(v0, h0, l0); split_bf16(v1, h1, l1);
                __nv_bfloat162 hp, lp;
                hp.x = h0; hp.y = h1; lp.x = l0; lp.y = l1;
                *(__nv_bfloat162*)(Ohi + (size_t)r0*Nn + cc) = hp;
                *(__nv_bfloat162*)(Olo + (size_t)r0*Nn + cc) = lp;
                split_bf16(v2, h0, l0); split_bf16(v3, h1, l1);
                hp.x = h0; hp.y = h1; lp.x = l0; lp.y = l1;
                *(__nv_bfloat162*)(Ohi + (size_t)(r0+8)*Nn + cc) = hp;
                *(__nv_bfloat162*)(Olo + (size_t)(r0+8)*Nn + cc) = lp;
            } else {
                float* p0 = C + (size_t)r0*Nn + cc;
                float* p1 = C + (size_t)(r0 + 8)*Nn + cc;
                if (VAR == 2) {
                    float2 o0 = *(float2*)p0, o1 = *(float2*)p1;
                    v0 += o0.x; v1 += o0.y; v2 += o1.x; v3 += o1.y;
                }
                *(float2*)p0 = make_float2(v0, v1);
                *(float2*)p1 = make_float2(v2, v3);
            }
        }
    }
}

/* ------------------------------------------------------------------ */
/* fused attention: 512 threads per (b,h); fp32 math                   */
/* K tile bank-swizzled (u ^= (u>>2)&7 on 16B units) -> conflict-free  */
/* output written as bf16 hi/lo into g_a_{hi,lo}                       */
/* ------------------------------------------------------------------ */
#define KS_LD 516
#define ATT_KS 0
#define ATT_VS 16512                       /* 32*516 */
#define ATT_QS 32896                       /* +512*32 */
#define ATT_PC 34944                       /* +16*128 */
#define ATTN_SMEM_FLOATS (34944 + 16*512)
#define ATTN_SMEM_BYTES  (ATTN_SMEM_FLOATS*4)

__global__ void __launch_bounds__(512)
attn_kernel(const float* __restrict__ edge_emb) {
    extern __shared__ __align__(16) float sm[];
    float* Ks = sm + ATT_KS;                 /* [32][516] transposed, swizzled */
    float* Vs = sm + ATT_VS;                 /* [512][32]            */
    float* qs = sm + ATT_QS;                 /* [16][128]            */

    const int bh = blockIdx.x;
    const int b  = bh >> 3, h = bh & 7;
    const int t  = threadIdx.x;
    const int w  = t >> 5, lane = t & 31;

    const float eb0 = edge_emb[0*HH + h];
    const float eb1 = edge_emb[1*HH + h];
    const float eb2 = edge_emb[2*HH + h];

    const float* base = g_qkv + ((size_t)b*SS)*768 + h*HDIM;
    for (int it = 0; it < 32; ++it) {
        int s = it*16 + w;
        int u = s >> 2, sub = s & 3;
        int up = u ^ ((u >> 2) & 7);
        Ks[lane*KS_LD + (up<<2) + sub] = base[(size_t)s*768 + 256 + lane];
        Vs[s*32 + lane]               = base[(size_t)s*768 + 512 + lane];
    }
    __syncthreads();

    /* swizzled per-lane K offsets (16 consecutive keys -> 4 float4s) */
    const int ko0 = (((lane<<2)+0) ^ (lane&7)) << 2;
    const int ko1 = (((lane<<2)+1) ^ (lane&7)) << 2;
    const int ko2 = (((lane<<2)+2) ^ (lane&7)) << 2;
    const int ko3 = (((lane<<2)+3) ^ (lane&7)) << 2;

    float* pcw = sm + ATT_PC + w*512;
    float* qw  = qs + w*128;
    const float inv = 0.17677669529663687f;

    for (int gi = 0; gi < 8; ++gi) {
        const int q0 = (gi*16 + w)*4;
#pragma unroll
        for (int r = 0; r < 4; ++r)
            qw[lane*4 + r] = base[(size_t)(q0 + r)*768 + lane];
        __syncwarp();

        ull acc[16][2];
#pragma unroll
        for (int j = 0; j < 16; ++j) { acc[j][0] = pk2(0.f,0.f); acc[j][1] = pk2(0.f,0.f); }

#pragma unroll 4
        for (int d = 0; d < 32; ++d) {
            float4 qv = *(const float4*)&qw[d*4];
            ull qp0 = pk2(qv.x, qv.y), qp1 = pk2(qv.z, qv.w);
            const float* kr = &Ks[d*KS_LD];
            float4 k0 = *(const float4*)(kr + ko0);
            float4 k1 = *(const float4*)(kr + ko1);
            float4 k2 = *(const float4*)(kr + ko2);
            float4 k3 = *(const float4*)(kr + ko3);
            float kvals[16] = {k0.x,k0.y,k0.z,k0.w, k1.x,k1.y,k1.z,k1.w,
                               k2.x,k2.y,k2.z,k2.w, k3.x,k3.y,k3.z,k3.w};
#pragma unroll
            for (int j = 0; j < 16; ++j) {
                ull bd = pk2(kvals[j], kvals[j]);
                acc[j][0] = ffma2(qp0, bd, acc[j][0]);
                acc[j][1] = ffma2(qp1, bd, acc[j][1]);
            }
        }

        float pbuf[4][16];
#pragma unroll
        for (int j = 0; j < 16; ++j) {
            float2 fa = upk2(acc[j][0]);
            float2 fb = upk2(acc[j][1]);
            pbuf[0][j] = fa.x; pbuf[1][j] = fa.y; pbuf[2][j] = fb.x; pbuf[3][j] = fb.y;
        }

#pragma unroll
        for (int r = 0; r < 4; ++r) {
            int q = q0 + r;
            if (q > 0) {
                const unsigned char* etr = g_et + ((size_t)(b*NNODE + (q-1)))*512;
                uint4 ev = *(const uint4*)(etr + lane*16);
                unsigned int wd[4] = {ev.x, ev.y, ev.z, ev.w};
                unsigned int last = (ev.w >> 24) & 0xffu;
                unsigned int prev = __shfl_up_sync(0xffffffffu, last, 1);
#pragma unroll
                for (int j = 0; j < 16; ++j) {
                    float bi;
                    if (j == 0) {
                        bi = (lane == 0) ? 0.f
                             : (prev == 0u ? eb0 : (prev == 1u ? eb1 : eb2));
                    } else {
                        unsigned int e = (wd[(j-1)>>2] >> (8*((j-1)&3))) & 0xffu;
                        bi = (e == 0u ? eb0 : (e == 1u ? eb1 : eb2));
                    }
                    pbuf[r][j] = pbuf[r][j]*inv + bi;
                }
            } else {
#pragma unroll
                for (int j = 0; j < 16; ++j) pbuf[r][j] *= inv;
            }
        }

#pragma unroll
        for (int r = 0; r < 4; ++r) {
            float m = -1e30f;
#pragma unroll
            for (int j = 0; j < 16; ++j) m = fmaxf(m, pbuf[r][j]);
#pragma unroll
            for (int o = 16; o; o >>= 1) m = fmaxf(m, __shfl_xor_sync(0xffffffffu, m, o));
            float s = 0.f;
#pragma unroll
            for (int j = 0; j < 16; ++j) { pbuf[r][j] = __expf(pbuf[r][j] - m); s += pbuf[r][j]; }
#pragma unroll
            for (int o = 16; o; o >>= 1) s += __shfl_xor_sync(0xffffffffu, s, o);
            float is = 1.f / s;
#pragma unroll
            for (int j = 0; j < 16; ++j) pbuf[r][j] *= is;
        }

        /* PV in 4 chunks of 4 j-slots: fp32 probs through 2KB/warp buffer */
        ull a01 = pk2(0.f,0.f), a23 = pk2(0.f,0.f);
#pragma unroll
        for (int c = 0; c < 4; ++c) {
#pragma unroll
            for (int jj = 0; jj < 4; ++jj) {
                int j = c*4 + jj;
                *(float4*)&pcw[(jj*32 + lane)*4] =
                    make_float4(pbuf[0][j], pbuf[1][j], pbuf[2][j], pbuf[3][j]);
            }
            __syncwarp();
#pragma unroll 4
            for (int s = 0; s < 128; ++s) {
                float4 pv = *(const float4*)&pcw[s*4];
                int key = ((s & 31) << 4) + c*4 + (s >> 5);
                float v = Vs[key*32 + lane];
                ull vd = pk2(v, v);
                a01 = ffma2(pk2(pv.x, pv.y), vd, a01);
                a23 = ffma2(pk2(pv.z, pv.w), vd, a23);
            }
            __syncwarp();
        }
        float2 oa = upk2(a01), ob = upk2(a23);
        float vals[4] = {oa.x, oa.y, ob.x, ob.y};
        size_t obase = ((size_t)b*SS + q0)*DD + h*HDIM + lane;
#pragma unroll
        for (int r = 0; r < 4; ++r) {
            __nv_bfloat16 hh, ll;
            split_bf16(vals[r], hh, ll);
            g_a_hi[obase + (size_t)r*DD] = hh;
            g_a_lo[obase + (size_t)r*DD] = ll;
        }
        __syncwarp();
    }
}

/* ------------------------------------------------------------------ */
/* head                                                                */
/* ------------------------------------------------------------------ */
__global__ void head_kernel(const float* __restrict__ fc1w, const float* __restrict__ fc1b,
                            const float* __restrict__ polw, const float* __restrict__ polb,
                            const float* __restrict__ valw, const float* __restrict__ valb,
                            float* __restrict__ out) {
    __shared__ float gs[256];
    __shared__ float os[64];
    int b = blockIdx.x, t = threadIdx.x;
    const float* xr = g_x + ((size_t)b*SS)*DD;
#pragma unroll
    for (int i = 0; i < 4; ++i) gs[t + i*64] = xr[t + i*64];
    __syncthreads();
    float a = fc1b[t];
#pragma unroll 8
    for (int k = 0; k < 256; ++k) a += gs[k] * fc1w[t*256 + k];
    os[t] = fmaxf(a, 0.f);
    __syncthreads();
    if (t < 7) {
        float pacc = polb[t];
#pragma unroll
        for (int j = 0; j < 64; ++j) pacc += os[j] * polw[t*64 + j];
        out[b*7 + t] = pacc;
    }
    if (t == 7) {
        float va = valb[0];
#pragma unroll
        for (int j = 0; j < 64; ++j) va += os[j] * valw[j];
        out[BB*7 + b] = tanhf(va);
    }
}

/* ------------------------------------------------------------------ */
extern "C" void kernel_launch(void* const* d_in, const int* in_sizes, int n_in,
                              void* d_out, int out_size) {
    const int*   cs    = (const int*)d_in[0];
    const int*   etm   = (const int*)d_in[1];
    const float* pe    = (const float*)d_in[2];
    const float* gt    = (const float*)d_in[3];
    const float* ee    = (const float*)d_in[4];
    const float* in_w  = (const float*)d_in[5];
    const float* in_b  = (const float*)d_in[6];
    const float* outw  = (const float*)d_in[7];
    const float* outb  = (const float*)d_in[8];
    const float* ff1w  = (const float*)d_in[9];
    const float* ff1b  = (const float*)d_in[10];
    const float* ff2w  = (const float*)d_in[11];
    const float* ff2b  = (const float*)d_in[12];
    const float* ln1g  = (const float*)d_in[13];
    const float* ln1b  = (const float*)d_in[14];
    const float* ln2g  = (const float*)d_in[15];
    const float* ln2b  = (const float*)d_in[16];
    const float* fc1w  = (const float*)d_in[17];
    const float* fc1b  = (const float*)d_in[18];
    const float* polw  = (const float*)d_in[19];
    const float* polb  = (const float*)d_in[20];
    const float* valw  = (const float*)d_in[21];
    const float* valb  = (const float*)d_in[22];
    float* out = (float*)d_out;

    float *px, *pq;
    __nv_bfloat16 *pah, *pal, *pfh, *pfl, *pwh, *pwl;
    cudaGetSymbolAddress((void**)&px,  g_x);
    cudaGetSymbolAddress((void**)&pq,  g_qkv);
    cudaGetSymbolAddress((void**)&pah, g_a_hi);
    cudaGetSymbolAddress((void**)&pal, g_a_lo);
    cudaGetSymbolAddress((void**)&pfh, g_f_hi);
    cudaGetSymbolAddress((void**)&pfl, g_f_lo);
    cudaGetSymbolAddress((void**)&pwh, g_w_hi);
    cudaGetSymbolAddress((void**)&pwl, g_w_lo);

    cudaFuncSetAttribute(attn_kernel, cudaFuncAttributeMaxDynamicSharedMemorySize,
                         ATTN_SMEM_BYTES);
    cudaFuncSetAttribute(gemm_bf<0,0>, cudaFuncAttributeMaxDynamicSharedMemorySize, GEMM_SMEM_BYTES);
    cudaFuncSetAttribute(gemm_bf<2,0>, cudaFuncAttributeMaxDynamicSharedMemorySize, GEMM_SMEM_BYTES);
    cudaFuncSetAttribute(gemm_bf<1,1>, cudaFuncAttributeMaxDynamicSharedMemorySize, GEMM_SMEM_BYTES);

    embed_kernel<<<MTOK, 256>>>(cs, pe, gt);
    etcomp_kernel<<<(BB*NNODE*NNODE + 255)/256, 256>>>(etm);

    /* weight hi/lo split (cheap; rerun every call for determinism) */
    wconv_kernel<<<(786432 + 255)/256, 256>>>(in_w,  786432, 0);
    wconv_kernel<<<(262144 + 255)/256, 256>>>(outw,  262144, 786432);
    wconv_kernel<<<(524288 + 255)/256, 256>>>(ff1w,  524288, 1048576);
    wconv_kernel<<<(524288 + 255)/256, 256>>>(ff2w,  524288, 1572864);

    for (int i = 0; i < LNUM; ++i) {
        const int inoff  = 0       + i*196608;
        const int outoff = 786432  + i*65536;
        const int f1off  = 1048576 + i*131072;
        const int f2off  = 1572864 + i*131072;

        ln_kernel<<<MTOK/8, 256>>>(ln1g + i*DD, ln1b + i*DD);
        gemm_bf<0,0><<<dim3(6, 256), 256, GEMM_SMEM_BYTES>>>(
            pah, pal, pwh + inoff, pwl + inoff, in_b + i*768, pq,
            (__nv_bfloat16*)0, (__nv_bfloat16*)0, 768, 256);
        attn_kernel<<<BB*HH, 512, ATTN_SMEM_BYTES>>>(ee);
        gemm_bf<2,0><<<dim3(2, 256), 256, GEMM_SMEM_BYTES>>>(
            pah, pal, pwh + outoff, pwl + outoff, outb + i*256, px,
            (__nv_bfloat16*)0, (__nv_bfloat16*)0, 256, 256);
        ln_kernel<<<MTOK/8, 256>>>(ln2g + i*DD, ln2b + i*DD);
        gemm_bf<1,1><<<dim3(4, 256), 256, GEMM_SMEM_BYTES>>>(
            pah, pal, pwh + f1off, pwl + f1off, ff1b + i*512, (float*)0,
            pfh, pfl, 512, 256);
        gemm_bf<2,0><<<dim3(2, 256), 256, GEMM_SMEM_BYTES>>>(
            pfh, pfl, pwh + f2off, pwl + f2off, ff2b + i*256, px,
            (__nv_bfloat16*)0, (__nv_bfloat16*)0, 256, 512);
    }
    head_kernel<<<BB, 64>>>(fc1w, fc1b, polw, polb, valw, valb, out);
}

// round 10
// speedup vs baseline: 3.1952x; 1.6895x over previous
#include <cuda_runtime.h>
#include <cuda_bf16.h>
#include <math.h>
#include <stdint.h>

#define LNUM 4
#define BB   64
#define NNODE 511
#define SS   512
#define DD   256
#define HH   8
#define HDIM 32
#define DFFN 512
#define MTOK (BB*SS)          /* 32768 */

typedef unsigned long long ull;

/* ------------------------------------------------------------------ */
/* Scratch (device globals; no allocations allowed)                    */
/* ------------------------------------------------------------------ */
__device__ float g_x  [(size_t)MTOK*DD];          /* residual stream  */
__device__ float g_qkv[(size_t)MTOK*3*DD];        /* qkv fp32         */
__device__ __nv_bfloat16 g_a_hi[(size_t)MTOK*DD]; /* activation hi    */
__device__ __nv_bfloat16 g_a_lo[(size_t)MTOK*DD]; /* activation lo    */
__device__ __nv_bfloat16 g_f_hi[(size_t)MTOK*DFFN];
__device__ __nv_bfloat16 g_f_lo[(size_t)MTOK*DFFN];
#define WTOT 2097152
__device__ __nv_bfloat16 g_w_hi[WTOT];
__device__ __nv_bfloat16 g_w_lo[WTOT];
/* per-head bias table: [b][h][q][k] bf16 (256MB) */
__device__ __nv_bfloat16 g_bias[(size_t)BB*HH*SS*SS];

/* ------------------------------------------------------------------ */
/* helpers                                                             */
/* ------------------------------------------------------------------ */
__device__ __forceinline__ uint32_t smem_u32(const void* p) {
    return (uint32_t)__cvta_generic_to_shared((void*)p);
}
__device__ __forceinline__ void split_bf16(float v, __nv_bfloat16& h, __nv_bfloat16& l) {
    h = __float2bfloat16(v);
    l = __float2bfloat16(v - __bfloat162float(h));
}
__device__ __forceinline__ uint32_t pkbf(__nv_bfloat16 a, __nv_bfloat16 b) {
    __nv_bfloat162 t; t.x = a; t.y = b;
    return *(uint32_t*)&t;
}
__device__ __forceinline__ void cp_async16(uint32_t dst, const void* src) {
    asm volatile("cp.async.cg.shared.global [%0], [%1], 16;" :: "r"(dst), "l"(src));
}
__device__ __forceinline__ void cp_commit() {
    asm volatile("cp.async.commit_group;" ::: "memory");
}
template<int N> __device__ __forceinline__ void cp_wait() {
    asm volatile("cp.async.wait_group %0;" :: "n"(N) : "memory");
}
__device__ __forceinline__ void ldsm4(uint32_t* r, uint32_t a) {
    asm volatile("ldmatrix.sync.aligned.m8n8.x4.shared.b16 {%0,%1,%2,%3}, [%4];"
                 : "=r"(r[0]), "=r"(r[1]), "=r"(r[2]), "=r"(r[3]) : "r"(a));
}
__device__ __forceinline__ void mma_bf16(float* c, const uint32_t* a,
                                         uint32_t b0, uint32_t b1) {
    asm volatile(
        "mma.sync.aligned.m16n8k16.row.col.f32.bf16.bf16.f32 "
        "{%0,%1,%2,%3}, {%4,%5,%6,%7}, {%8,%9}, {%0,%1,%2,%3};"
        : "+f"(c[0]), "+f"(c[1]), "+f"(c[2]), "+f"(c[3])
        : "r"(a[0]), "r"(a[1]), "r"(a[2]), "r"(a[3]), "r"(b0), "r"(b1));
}

/* ------------------------------------------------------------------ */
/* embed + bias table build + weight split                             */
/* ------------------------------------------------------------------ */
__global__ void embed_kernel(const int* __restrict__ cs,
                             const float* __restrict__ patch_emb,
                             const float* __restrict__ game_token) {
    int row = blockIdx.x;
    int d   = threadIdx.x;
    int b = row >> 9, s = row & 511;
    float v;
    if (s == 0) v = game_token[d];
    else        v = patch_emb[cs[b*NNODE + s - 1]*DD + d];
    g_x[(size_t)row*DD + d] = v;
}

/* bias[b][h][q][k] = (q==0||k==0) ? 0 : edge_emb[etm[b][q-1][k-1]][h] */
__global__ void gbias_kernel(const int* __restrict__ etm,
                             const float* __restrict__ ee) {
    int q = blockIdx.x, b = blockIdx.y, t = threadIdx.x;
    int k0 = 2*t, k1 = 2*t + 1;
    int t0 = 3, t1 = 3;
    if (q > 0) {
        const int* er = etm + ((size_t)b*NNODE + (q-1))*NNODE;
        if (k0 > 0) t0 = er[k0 - 1];
        t1 = er[k1 - 1];
    }
#pragma unroll
    for (int h = 0; h < HH; ++h) {
        float b0 = (t0 < 3) ? ee[t0*HH + h] : 0.f;
        float b1 = (t1 < 3) ? ee[t1*HH + h] : 0.f;
        uint32_t pv = pkbf(__float2bfloat16(b0), __float2bfloat16(b1));
        size_t off = (((size_t)(b*HH + h)*SS + q) << 9) + k0;
        *(uint32_t*)(g_bias + off) = pv;
    }
}

__global__ void wconv_kernel(const float* __restrict__ src, int n, int off) {
    int i = blockIdx.x*256 + threadIdx.x;
    if (i >= n) return;
    float x = src[i];
    __nv_bfloat16 h, l; split_bf16(x, h, l);
    g_w_hi[off + i] = h;
    g_w_lo[off + i] = l;
}

/* ------------------------------------------------------------------ */
/* layernorm: g_a_{hi,lo} = split(LN(g_x)*g + b)   (one warp per row)  */
/* ------------------------------------------------------------------ */
__global__ void ln_kernel(const float* __restrict__ gam, const float* __restrict__ bet) {
    int w = threadIdx.x >> 5, lane = threadIdx.x & 31;
    int row = blockIdx.x*8 + w;
    const float* xr = g_x + (size_t)row*DD;
    float4 v0 = *(const float4*)(xr + lane*8);
    float4 v1 = *(const float4*)(xr + lane*8 + 4);
    float s = v0.x+v0.y+v0.z+v0.w + v1.x+v1.y+v1.z+v1.w;
    float q = v0.x*v0.x+v0.y*v0.y+v0.z*v0.z+v0.w*v0.w
            + v1.x*v1.x+v1.y*v1.y+v1.z*v1.z+v1.w*v1.w;
#pragma unroll
    for (int o = 16; o; o >>= 1) {
        s += __shfl_xor_sync(0xffffffffu, s, o);
        q += __shfl_xor_sync(0xffffffffu, q, o);
    }
    float m   = s * (1.f/256.f);
    float var = q * (1.f/256.f) - m*m;
    float rs  = rsqrtf(var + 1e-5f);
    int d = lane*8;
    float4 ga = *(const float4*)(gam + d);
    float4 gb = *(const float4*)(gam + d + 4);
    float4 ba = *(const float4*)(bet + d);
    float4 bb = *(const float4*)(bet + d + 4);
    float o8[8];
    o8[0] = (v0.x-m)*rs*ga.x + ba.x;  o8[1] = (v0.y-m)*rs*ga.y + ba.y;
    o8[2] = (v0.z-m)*rs*ga.z + ba.z;  o8[3] = (v0.w-m)*rs*ga.w + ba.w;
    o8[4] = (v1.x-m)*rs*gb.x + bb.x;  o8[5] = (v1.y-m)*rs*gb.y + bb.y;
    o8[6] = (v1.z-m)*rs*gb.z + bb.z;  o8[7] = (v1.w-m)*rs*gb.w + bb.w;
    __nv_bfloat16* hh = g_a_hi + (size_t)row*DD + d;
    __nv_bfloat16* ll = g_a_lo + (size_t)row*DD + d;
#pragma unroll
    for (int p = 0; p < 4; ++p) {
        __nv_bfloat16 h0, l0, h1, l1;
        split_bf16(o8[2*p],   h0, l0);
        split_bf16(o8[2*p+1], h1, l1);
        *(uint32_t*)(hh + 2*p) = pkbf(h0, h1);
        *(uint32_t*)(ll + 2*p) = pkbf(l0, l1);
    }
}

/* ------------------------------------------------------------------ */
/* bf16 tensor-core GEMM (unchanged from r9)                           */
/* ------------------------------------------------------------------ */
#define GEMM_SMEM_BYTES (2*32768)

template<int VAR, int WB>
__global__ void __launch_bounds__(256)
gemm_bf(const __nv_bfloat16* __restrict__ Ahi, const __nv_bfloat16* __restrict__ Alo,
        const __nv_bfloat16* __restrict__ Whi, const __nv_bfloat16* __restrict__ Wlo,
        const float* __restrict__ bias, float* __restrict__ C,
        __nv_bfloat16* __restrict__ Ohi, __nv_bfloat16* __restrict__ Olo,
        int Nn, int K)
{
    extern __shared__ __align__(16) __nv_bfloat16 smb[];
    const int t    = threadIdx.x;
    const int lane = t & 31;
    const int wid  = t >> 5;
    const int wm   = wid & 1;
    const int wn   = wid >> 1;
    const int m0   = blockIdx.y * 128;
    const int n0   = blockIdx.x * 128;
    const int NC   = K >> 5;
    const uint32_t sb = smem_u32(smb);

    const __nv_bfloat16* mp[4] = {
        Ahi + (size_t)m0*K, Alo + (size_t)m0*K,
        Whi + (size_t)n0*K, Wlo + (size_t)n0*K };

    int cid_mi[8], cid_r[8], cid_cs[8];
#pragma unroll
    for (int i = 0; i < 8; ++i) {
        int id = i*256 + t;
        cid_mi[i] = id >> 9;
        int rem = id & 511;
        cid_r[i]  = rem >> 2;
        cid_cs[i] = rem & 3;
    }

    float acc[4][4][4];
#pragma unroll
    for (int i = 0; i < 4; ++i)
#pragma unroll
        for (int j = 0; j < 4; ++j)
#pragma unroll
            for (int q = 0; q < 4; ++q) acc[i][j][q] = 0.f;

    {
        uint32_t dbase = sb;
#pragma unroll
        for (int i = 0; i < 8; ++i) {
            int r = cid_r[i], cs = cid_cs[i], mi = cid_mi[i];
            uint32_t dst = dbase + mi*8192 + r*64 + ((cs ^ ((r>>1)&3))<<4);
            cp_async16(dst, mp[mi] + (size_t)r*K + cs*8);
        }
        cp_commit();
    }

    const int lr = lane & 15;
    const int lc = lane >> 4;

    for (int c = 0; c < NC; ++c) {
        if (c + 1 < NC) {
            int kc = (c+1) << 5;
            uint32_t dbase = sb + ((c+1)&1)*32768;
#pragma unroll
            for (int i = 0; i < 8; ++i) {
                int r = cid_r[i], cs = cid_cs[i], mi = cid_mi[i];
                uint32_t dst = dbase + mi*8192 + r*64 + ((cs ^ ((r>>1)&3))<<4);
                cp_async16(dst, mp[mi] + (size_t)r*K + kc + cs*8);
            }
            cp_commit();
            cp_wait<1>();
        } else {
            cp_wait<0>();
        }
        __syncthreads();

        uint32_t bb = sb + (c&1)*32768;
#pragma unroll
        for (int ks = 0; ks < 2; ++ks) {
            int cseg = ks*2 + lc;
            uint32_t bh[2][4], bl[2][4];
#pragma unroll
            for (int np = 0; np < 2; ++np) {
                int r = wn*32 + np*16 + lr;
                uint32_t off = r*64 + ((cseg ^ ((r>>1)&3))<<4);
                ldsm4(bh[np], bb + 2*8192 + off);
                ldsm4(bl[np], bb + 3*8192 + off);
            }
#pragma unroll
            for (int mt = 0; mt < 4; ++mt) {
                int r = wm*64 + mt*16 + lr;
                uint32_t off = r*64 + ((cseg ^ ((r>>1)&3))<<4);
                uint32_t ah[4], al[4];
                ldsm4(ah, bb + off);
                ldsm4(al, bb + 8192 + off);
#pragma unroll
                for (int nt = 0; nt < 4; ++nt) {
                    int np = nt >> 1, h2 = nt & 1;
                    mma_bf16(acc[mt][nt], ah, bh[np][h2], bh[np][h2+2]);
                    mma_bf16(acc[mt][nt], ah, bl[np][h2], bl[np][h2+2]);
                    mma_bf16(acc[mt][nt], al, bh[np][h2], bh[np][h2+2]);
                }
            }
        }
        __syncthreads();
    }

#pragma unroll
    for (int mt = 0; mt < 4; ++mt) {
#pragma unroll
        for (int nt = 0; nt < 4; ++nt) {
            int r0 = m0 + wm*64 + mt*16 + (lane >> 2);
            int cc = n0 + wn*32 + nt*8 + ((lane & 3) << 1);
            float b0 = bias[cc], b1 = bias[cc + 1];
            float v0 = acc[mt][nt][0] + b0;
            float v1 = acc[mt][nt][1] + b1;
            float v2 = acc[mt][nt][2] + b0;
            float v3 = acc[mt][nt][3] + b1;
            if (VAR == 1) {
                v0 = fmaxf(v0, 0.f); v1 = fmaxf(v1, 0.f);
                v2 = fmaxf(v2, 0.f); v3 = fmaxf(v3, 0.f);
            }
            if (WB) {
                __nv_bfloat16 h0,l0,h1,l1;
                split_bf16(v0, h0, l0); split_bf16(v1, h1, l1);
                *(uint32_t*)(Ohi + (size_t)r0*Nn + cc) = pkbf(h0, h1);
                *(uint32_t*)(Olo + (size_t)r0*Nn + cc) = pkbf(l0, l1);
                split_bf16(v2, h0, l0); split_bf16(v3, h1, l1);
                *(uint32_t*)(Ohi + (size_t)(r0+8)*Nn + cc) = pkbf(h0, h1);
                *(uint32_t*)(Olo + (size_t)(r0+8)*Nn + cc) = pkbf(l0, l1);
            } else {
                float* p0 = C + (size_t)r0*Nn + cc;
                float* p1 = C + (size_t)(r0 + 8)*Nn + cc;
                if (VAR == 2) {
                    float2 o0 = *(float2*)p0, o1 = *(float2*)p1;
                    v0 += o0.x; v1 += o0.y; v2 += o1.x; v3 += o1.y;
                }
                *(float2*)p0 = make_float2(v0, v1);
                *(float2*)p1 = make_float2(v2, v3);
            }
        }
    }
}

/* ------------------------------------------------------------------ */
/* MMA flash attention: 256 threads (8 warps) per (b,h)                */
/* warp = 64 q-rows (4 mtiles); 16 key-chunks of 32; online softmax.   */
/* QK^T and PV both bf16 hi/lo (3 MMAs each). Bias from g_bias bf16.   */
/* ------------------------------------------------------------------ */
#define AQH 0
#define AQL 32768
#define AKH 65536
#define AKL 98304
#define AVH 131072
#define AVL 163840
#define ATT_SMEM 196608

__global__ void __launch_bounds__(256)
attn_mma() {
    extern __shared__ __align__(16) char smc[];
    const uint32_t sb = smem_u32(smc);
    const int bh = blockIdx.x;
    const int b = bh >> 3, h = bh & 7;
    const int t = threadIdx.x;
    const int w = t >> 5, lane = t & 31;

    const float* base = g_qkv + ((size_t)b*SS)*768 + h*HDIM;

    /* stage Q,K as swizzled [row][32]b (64B rows), V transposed [dim][512] */
    for (int i = t; i < 512*32; i += 256) {
        int s = i >> 5, d = i & 31;
        float qv = base[(size_t)s*768 + d];
        float kv = base[(size_t)s*768 + 256 + d];
        float vv = base[(size_t)s*768 + 512 + d];
        __nv_bfloat16 hh, ll;
        int qk_off = s*64 + (((d>>3) ^ (s&3))<<4) + (d&7)*2;
        split_bf16(qv, hh, ll);
        *(__nv_bfloat16*)(smc + AQH + qk_off) = hh;
        *(__nv_bfloat16*)(smc + AQL + qk_off) = ll;
        split_bf16(kv, hh, ll);
        *(__nv_bfloat16*)(smc + AKH + qk_off) = hh;
        *(__nv_bfloat16*)(smc + AKL + qk_off) = ll;
        split_bf16(vv, hh, ll);
        int vt_off = d*1024 + (((s>>3) ^ (d&7))<<4) + (s&7)*2;
        *(__nv_bfloat16*)(smc + AVH + vt_off) = hh;
        *(__nv_bfloat16*)(smc + AVL + vt_off) = ll;
    }
    __syncthreads();

    const int qw = w * 64;
    const int r1 = lane >> 2;
    const int c2 = (lane & 3) << 1;
    const float inv = 0.17677669529663687f;
    const __nv_bfloat16* gb = g_bias + ((size_t)(b*HH + h) << 18);

    float O[4][4][4];
    float mr[4][2], lr[4][2];
#pragma unroll
    for (int mt = 0; mt < 4; ++mt) {
#pragma unroll
        for (int dn = 0; dn < 4; ++dn)
#pragma unroll
            for (int q = 0; q < 4; ++q) O[mt][dn][q] = 0.f;
        mr[mt][0] = -1e30f; mr[mt][1] = -1e30f;
        lr[mt][0] = 0.f;    lr[mt][1] = 0.f;
    }

    const int tile = lane >> 3;

    for (int c = 0; c < 16; ++c) {
        float S[4][4][4];
#pragma unroll
        for (int mt = 0; mt < 4; ++mt)
#pragma unroll
            for (int nt = 0; nt < 4; ++nt)
#pragma unroll
                for (int q = 0; q < 4; ++q) S[mt][nt][q] = 0.f;

        /* ---- QK^T ---- */
#pragma unroll
        for (int ks = 0; ks < 2; ++ks) {
            uint32_t bkh[4][2], bkl[4][2];
#pragma unroll
            for (int np = 0; np < 2; ++np) {
                int nt = np*2 + (tile >> 1);
                int key = c*32 + nt*8 + (lane & 7);
                int seg = ks*2 + (tile & 1);
                uint32_t addr = sb + AKH + key*64 + ((seg ^ (key & 3))<<4);
                uint32_t r4[4];
                ldsm4(r4, addr);
                bkh[np*2][0] = r4[0]; bkh[np*2][1] = r4[1];
                bkh[np*2+1][0] = r4[2]; bkh[np*2+1][1] = r4[3];
                ldsm4(r4, addr + 32768);
                bkl[np*2][0] = r4[0]; bkl[np*2][1] = r4[1];
                bkl[np*2+1][0] = r4[2]; bkl[np*2+1][1] = r4[3];
            }
#pragma unroll
            for (int mt = 0; mt < 4; ++mt) {
                int rr = (tile & 1)*8 + (lane & 7);
                int row = qw + mt*16 + rr;
                int seg = ks*2 + (tile >> 1);
                uint32_t addr = sb + AQH + row*64 + ((seg ^ (row & 3))<<4);
                uint32_t aqh[4], aql[4];
                ldsm4(aqh, addr);
                ldsm4(aql, addr + 32768);
#pragma unroll
                for (int nt = 0; nt < 4; ++nt) {
                    mma_bf16(S[mt][nt], aqh, bkh[nt][0], bkh[nt][1]);
                    mma_bf16(S[mt][nt], aqh, bkl[nt][0], bkl[nt][1]);
                    mma_bf16(S[mt][nt], aql, bkh[nt][0], bkh[nt][1]);
                }
            }
        }

        /* ---- bias + scale + online softmax update ---- */
#pragma unroll
        for (int mt = 0; mt < 4; ++mt) {
#pragma unroll
            for (int h2 = 0; h2 < 2; ++h2) {
                int row = qw + mt*16 + h2*8 + r1;
                const __nv_bfloat16* gr = gb + (((size_t)row) << 9) + c*32 + c2;
                float vmax = -1e30f;
#pragma unroll
                for (int nt = 0; nt < 4; ++nt) {
                    uint32_t bp = *(const uint32_t*)(gr + nt*8);
                    __nv_bfloat162 b2 = *(__nv_bfloat162*)&bp;
                    float v0 = S[mt][nt][h2*2]   * inv + __bfloat162float(b2.x);
                    float v1 = S[mt][nt][h2*2+1] * inv + __bfloat162float(b2.y);
                    S[mt][nt][h2*2] = v0; S[mt][nt][h2*2+1] = v1;
                    vmax = fmaxf(vmax, fmaxf(v0, v1));
                }
                vmax = fmaxf(vmax, __shfl_xor_sync(0xffffffffu, vmax, 1));
                vmax = fmaxf(vmax, __shfl_xor_sync(0xffffffffu, vmax, 2));
                float mo = mr[mt][h2];
                float mn = fmaxf(mo, vmax);
                float alpha = __expf(mo - mn);
                mr[mt][h2] = mn;
                float rs = 0.f;
#pragma unroll
                for (int nt = 0; nt < 4; ++nt) {
                    float p0 = __expf(S[mt][nt][h2*2]   - mn);
                    float p1 = __expf(S[mt][nt][h2*2+1] - mn);
                    S[mt][nt][h2*2] = p0; S[mt][nt][h2*2+1] = p1;
                    rs += p0 + p1;
                }
                rs += __shfl_xor_sync(0xffffffffu, rs, 1);
                rs += __shfl_xor_sync(0xffffffffu, rs, 2);
                lr[mt][h2] = lr[mt][h2]*alpha + rs;
#pragma unroll
                for (int dn = 0; dn < 4; ++dn) {
                    O[mt][dn][h2*2]   *= alpha;
                    O[mt][dn][h2*2+1] *= alpha;
                }
            }
        }

        /* ---- PV ---- */
#pragma unroll
        for (int j = 0; j < 2; ++j) {
            uint32_t bvh[4][2], bvl[4][2];
#pragma unroll
            for (int dp = 0; dp < 2; ++dp) {
                int dn = dp*2 + (tile >> 1);
                int dim = dn*8 + (lane & 7);
                int kseg = c*4 + j*2 + (tile & 1);
                uint32_t addr = sb + AVH + dim*1024 + ((kseg ^ (dim & 7))<<4);
                uint32_t r4[4];
                ldsm4(r4, addr);
                bvh[dp*2][0] = r4[0]; bvh[dp*2][1] = r4[1];
                bvh[dp*2+1][0] = r4[2]; bvh[dp*2+1][1] = r4[3];
                ldsm4(r4, addr + 32768);
                bvl[dp*2][0] = r4[0]; bvl[dp*2][1] = r4[1];
                bvl[dp*2+1][0] = r4[2]; bvl[dp*2+1][1] = r4[3];
            }
#pragma unroll
            for (int mt = 0; mt < 4; ++mt) {
                uint32_t ph[4], pl[4];
                float p00 = S[mt][2*j][0],   p01 = S[mt][2*j][1];
                float p02 = S[mt][2*j][2],   p03 = S[mt][2*j][3];
                float p10 = S[mt][2*j+1][0], p11 = S[mt][2*j+1][1];
                float p12 = S[mt][2*j+1][2], p13 = S[mt][2*j+1][3];
                __nv_bfloat16 h00 = __float2bfloat16(p00), h01 = __float2bfloat16(p01);
                __nv_bfloat16 h02 = __float2bfloat16(p02), h03 = __float2bfloat16(p03);
                __nv_bfloat16 h10 = __float2bfloat16(p10), h11 = __float2bfloat16(p11);
                __nv_bfloat16 h12 = __float2bfloat16(p12), h13 = __float2bfloat16(p13);
                ph[0] = pkbf(h00, h01); ph[1] = pkbf(h02, h03);
                ph[2] = pkbf(h10, h11); ph[3] = pkbf(h12, h13);
                pl[0] = pkbf(__float2bfloat16(p00 - __bfloat162float(h00)),
                             __float2bfloat16(p01 - __bfloat162float(h01)));
                pl[1] = pkbf(__float2bfloat16(p02 - __bfloat162float(h02)),
                             __float2bfloat16(p03 - __bfloat162float(h03)));
                pl[2] = pkbf(__float2bfloat16(p10 - __bfloat162float(h10)),
                             __float2bfloat16(p11 - __bfloat162float(h11)));
                pl[3] = pkbf(__float2bfloat16(p12 - __bfloat162float(h12)),
                             __float2bfloat16(p13 - __bfloat162float(h13)));
#pragma unroll
                for (int dn = 0; dn < 4; ++dn) {
                    mma_bf16(O[mt][dn], ph, bvh[dn][0], bvh[dn][1]);
                    mma_bf16(O[mt][dn], ph, bvl[dn][0], bvl[dn][1]);
                    mma_bf16(O[mt][dn], pl, bvh[dn][0], bvh[dn][1]);
                }
            }
        }
    }

    /* ---- finalize: O /= l, write bf16 hi/lo ---- */
#pragma unroll
    for (int mt = 0; mt < 4; ++mt) {
#pragma unroll
        for (int h2 = 0; h2 < 2; ++h2) {
            float il = 1.f / lr[mt][h2];
            int row = b*SS + qw + mt*16 + h2*8 + r1;
#pragma unroll
            for (int dn = 0; dn < 4; ++dn) {
                float v0 = O[mt][dn][h2*2]   * il;
                float v1 = O[mt][dn][h2*2+1] * il;
                __nv_bfloat16 h0, l0, h1, l1;
                split_bf16(v0, h0, l0);
                split_bf16(v1, h1, l1);
                int col = h*HDIM + dn*8 + c2;
                *(uint32_t*)(g_a_hi + (size_t)row*DD + col) = pkbf(h0, h1);
                *(uint32_t*)(g_a_lo + (size_t)row*DD + col) = pkbf(l0, l1);
            }
        }
    }
}

/* ------------------------------------------------------------------ */
/* head                                                                */
/* ------------------------------------------------------------------ */
__global__ void head_kernel(const float* __restrict__ fc1w, const float* __restrict__ fc1b,
                            const float* __restrict__ polw, const float* __restrict__ polb,
                            const float* __restrict__ valw, const float* __restrict__ valb,
                            float* __restrict__ out) {
    __shared__ float gs[256];
    __shared__ float os[64];
    int b = blockIdx.x, t = threadIdx.x;
    const float* xr = g_x + ((size_t)b*SS)*DD;
#pragma unroll
    for (int i = 0; i < 4; ++i) gs[t + i*64] = xr[t + i*64];
    __syncthreads();
    float a = fc1b[t];
#pragma unroll 8
    for (int k = 0; k < 256; ++k) a += gs[k] * fc1w[t*256 + k];
    os[t] = fmaxf(a, 0.f);
    __syncthreads();
    if (t < 7) {
        float pacc = polb[t];
#pragma unroll
        for (int j = 0; j < 64; ++j) pacc += os[j] * polw[t*64 + j];
        out[b*7 + t] = pacc;
    }
    if (t == 7) {
        float va = valb[0];
#pragma unroll
        for (int j = 0; j < 64; ++j) va += os[j] * valw[j];
        out[BB*7 + b] = tanhf(va);
    }
}

/* ------------------------------------------------------------------ */
extern "C" void kernel_launch(void* const* d_in, const int* in_sizes, int n_in,
                              void* d_out, int out_size) {
    const int*   cs    = (const int*)d_in[0];
    const int*   etm   = (const int*)d_in[1];
    const float* pe    = (const float*)d_in[2];
    const float* gt    = (const float*)d_in[3];
    const float* ee    = (const float*)d_in[4];
    const float* in_w  = (const float*)d_in[5];
    const float* in_b  = (const float*)d_in[6];
    const float* outw  = (const float*)d_in[7];
    const float* outb  = (const float*)d_in[8];
    const float* ff1w  = (const float*)d_in[9];
    const float* ff1b  = (const float*)d_in[10];
    const float* ff2w  = (const float*)d_in[11];
    const float* ff2b  = (const float*)d_in[12];
    const float* ln1g  = (const float*)d_in[13];
    const float* ln1b  = (const float*)d_in[14];
    const float* ln2g  = (const float*)d_in[15];
    const float* ln2b  = (const float*)d_in[16];
    const float* fc1w  = (const float*)d_in[17];
    const float* fc1b  = (const float*)d_in[18];
    const float* polw  = (const float*)d_in[19];
    const float* polb  = (const float*)d_in[20];
    const float* valw  = (const float*)d_in[21];
    const float* valb  = (const float*)d_in[22];
    float* out = (float*)d_out;

    float *px, *pq;
    __nv_bfloat16 *pah, *pal, *pfh, *pfl, *pwh, *pwl;
    cudaGetSymbolAddress((void**)&px,  g_x);
    cudaGetSymbolAddress((void**)&pq,  g_qkv);
    cudaGetSymbolAddress((void**)&pah, g_a_hi);
    cudaGetSymbolAddress((void**)&pal, g_a_lo);
    cudaGetSymbolAddress((void**)&pfh, g_f_hi);
    cudaGetSymbolAddress((void**)&pfl, g_f_lo);
    cudaGetSymbolAddress((void**)&pwh, g_w_hi);
    cudaGetSymbolAddress((void**)&pwl, g_w_lo);

    cudaFuncSetAttribute(attn_mma, cudaFuncAttributeMaxDynamicSharedMemorySize, ATT_SMEM);
    cudaFuncSetAttribute(gemm_bf<0,0>, cudaFuncAttributeMaxDynamicSharedMemorySize, GEMM_SMEM_BYTES);
    cudaFuncSetAttribute(gemm_bf<2,0>, cudaFuncAttributeMaxDynamicSharedMemorySize, GEMM_SMEM_BYTES);
    cudaFuncSetAttribute(gemm_bf<1,1>, cudaFuncAttributeMaxDynamicSharedMemorySize, GEMM_SMEM_BYTES);

    embed_kernel<<<MTOK, 256>>>(cs, pe, gt);
    gbias_kernel<<<dim3(512, 64), 256>>>(etm, ee);

    wconv_kernel<<<(786432 + 255)/256, 256>>>(in_w,  786432, 0);
    wconv_kernel<<<(262144 + 255)/256, 256>>>(outw,  262144, 786432);
    wconv_kernel<<<(524288 + 255)/256, 256>>>(ff1w,  524288, 1048576);
    wconv_kernel<<<(524288 + 255)/256, 256>>>(ff2w,  524288, 1572864);

    for (int i = 0; i < LNUM; ++i) {
        const int inoff  = 0       + i*196608;
        const int outoff = 786432  + i*65536;
        const int f1off  = 1048576 + i*131072;
        const int f2off  = 1572864 + i*131072;

        ln_kernel<<<MTOK/8, 256>>>(ln1g + i*DD, ln1b + i*DD);
        gemm_bf<0,0><<<dim3(6, 256), 256, GEMM_SMEM_BYTES>>>(
            pah, pal, pwh + inoff, pwl + inoff, in_b + i*768, pq,
            (__nv_bfloat16*)0, (__nv_bfloat16*)0, 768, 256);
        attn_mma<<<BB*HH, 256, ATT_SMEM>>>();
        gemm_bf<2,0><<<dim3(2, 256), 256, GEMM_SMEM_BYTES>>>(
            pah, pal, pwh + outoff, pwl + outoff, outb + i*256, px,
            (__nv_bfloat16*)0, (__nv_bfloat16*)0, 256, 256);
        ln_kernel<<<MTOK/8, 256>>>(ln2g + i*DD, ln2b + i*DD);
        gemm_bf<1,1><<<dim3(4, 256), 256, GEMM_SMEM_BYTES>>>(
            pah, pal, pwh + f1off, pwl + f1off, ff1b + i*512, (float*)0,
            pfh, pfl, 512, 256);
        gemm_bf<2,0><<<dim3(2, 256), 256, GEMM_SMEM_BYTES>>>(
            pfh, pfl, pwh + f2off, pwl + f2off, ff2b + i*256, px,
            (__nv_bfloat16*)0, (__nv_bfloat16*)0, 256, 512);
    }
    head_kernel<<<BB, 64>>>(fc1w, fc1b, polw, polb, valw, valb, out);
}